// round 16
// baseline (speedup 1.0000x reference)
#include <cuda_runtime.h>
#include <cstdint>

#define T_DIM    2000
#define KFR      400
#define KD       400
#define A_DIM    100
#define NSLOT    100000                // 8-row slots total (800000 rows)
#define GRID     1036                  // 7 blocks/SM * 148 SMs: exact capacity
#define NWARPS   (GRID * 4)            // 4144
#define BASEW    24                    // NSLOT / NWARPS
#define EXTRA    544                   // first 544 warps get 25 slots
#define SLOT_X   3200                  // 8 rows * 400B (one bulk DMA)
#define SLOT_SZ  3264                  // + 32B mask + pad (16B aligned)
#define TXB      3232u
#define OFF_TH   (4 * 2 * SLOT_SZ)                 // 26112
#define OFF_AH   (OFF_TH + 416)                    // 26528
#define OFF_MBAR (OFF_AH + 512)                    // 27040
#define DYN_SZ   (OFF_MBAR + 64)                   // 27104
#define EPSF     1e-24f

typedef unsigned long long u64;

__device__ __forceinline__ u64 pack2(float lo, float hi) {
    u64 r; asm("mov.b64 %0, {%1, %2};" : "=l"(r) : "f"(lo), "f"(hi)); return r;
}
__device__ __forceinline__ void unpack2(u64 v, float& lo, float& hi) {
    asm("mov.b64 {%0, %1}, %2;" : "=f"(lo), "=f"(hi) : "l"(v));
}
__device__ __forceinline__ u64 ffma2(u64 a, u64 b, u64 c) {
    u64 d; asm("fma.rn.f32x2 %0, %1, %2, %3;" : "=l"(d) : "l"(a), "l"(b), "l"(c));
    return d;
}
__device__ __forceinline__ void mbar_wait(uint32_t mbar, uint32_t parity) {
    asm volatile(
        "{\n\t.reg .pred P;\n\t"
        "W_%=:\n\t"
        "mbarrier.try_wait.parity.acquire.cta.shared::cta.b64 P, [%0], %1, 0x989680;\n\t"
        "@!P bra W_%=;\n\t}"
        :: "r"(mbar), "r"(parity) : "memory");
}

// Accumulators: [0..99]=Ga, [100..199]=Ha, [200]=P1, [201]=P2. Self-cleaning.
__device__ float d_acc[2 * A_DIM + 2];
__device__ unsigned int d_done;

// R15's 8-row 3.2KB slots, but with the grid that actually REALIZES the
// occupancy: 1036 blocks = 7 blocks/SM exact capacity (R15 kept GRID=592,
// so 8-blocks/SM residency never existed and occ stayed 24%). 28 warps/SM.
// Per-warp 2-deep private mbarrier ring (no block sync), static balanced
// 24/25-consecutive-slot ranges (tail grain ~0.65us, imbalance ~4%).
// PASS 1: row's 100-dot split across 4 lanes (7/6/6/6 FFMA2 chunks), two
// shfl_xor(8,16) merge; ONE exp/log/div warp-op serves 8 rows; exact
// per-lane phi_k. PASS 2: lane-per-column, (A,H) broadcast via LDS.64,
// 4 FFMA2 per row. Fused last-block finalize, self-cleaning for replay.
__global__ __launch_bounds__(128) void mmdglm_main(
    const float* __restrict__ tg, const int* __restrict__ mask,
    const float* __restrict__ X, const float* __restrict__ theta,
    const float* __restrict__ phi_fr, const float* __restrict__ phi_d,
    float* __restrict__ out)
{
    extern __shared__ __align__(16) char dyn[];
    __shared__ float sga[4][A_DIM];
    __shared__ float sha[4][A_DIM];
    __shared__ float sp[4][2];

    const int warp  = threadIdx.x >> 5;
    const int lane  = threadIdx.x & 31;
    const int tid   = threadIdx.x;
    const float dt  = tg[1] - tg[0];
    const unsigned FULL = 0xffffffffu;
    const u64 Z64 = 0ull;

    const uint32_t dyn_b  = (uint32_t)__cvta_generic_to_shared(dyn);
    const uint32_t mbar_b = dyn_b + OFF_MBAR;

    // theta -> smem broadcast table
    if (tid < A_DIM) *(float*)(dyn + OFF_TH + tid * 4) = __ldg(theta + tid);

    if (tid < 8) {
        asm volatile("mbarrier.init.shared.b64 [%0], 1;"
                     :: "r"(mbar_b + tid * 8) : "memory");
    }
    asm volatile("fence.proxy.async.shared::cta;" ::: "memory");
    __syncthreads();

    // static balanced slot range for this warp
    const int gw      = blockIdx.x * 4 + warp;
    const int myStart = BASEW * gw + (gw < EXTRA ? gw : EXTRA);
    const int myCount = BASEW + (gw < EXTRA ? 1 : 0);

    const char* gX = (const char*)X;
    const char* gM = (const char*)mask;

    auto issue = [&](int g) {
        const int slot = g & 1;
        const uint32_t sd = dyn_b + (uint32_t)(warp * 2 + slot) * SLOT_SZ;
        const uint32_t mb = mbar_b + (uint32_t)(warp * 2 + slot) * 8;
        const size_t sid = (size_t)(myStart + g);
        asm volatile("mbarrier.arrive.expect_tx.shared.b64 _, [%0], %1;"
                     :: "r"(mb), "r"(TXB) : "memory");
        asm volatile("cp.async.bulk.shared::cta.global.mbarrier::complete_tx::bytes"
                     " [%0], [%1], %2, [%3];"
                     :: "r"(sd), "l"(gX + sid * SLOT_X), "n"(SLOT_X), "r"(mb) : "memory");
        asm volatile("cp.async.bulk.shared::cta.global.mbarrier::complete_tx::bytes"
                     " [%0], [%1], %2, [%3];"
                     :: "r"(sd + SLOT_X), "l"(gM + sid * 32), "n"(32), "r"(mb) : "memory");
    };

    if (lane == 0) { issue(0); if (myCount > 1) issue(1); }

    u64 Ga01 = Z64, Ga23 = Z64, Ha01 = Z64, Ha23 = Z64;
    float p1acc = 0.f, p2acc = 0.f;

    const ulonglong2* thp = (const ulonglong2*)(dyn + OFF_TH);
    float2* ahp = (float2*)(dyn + OFF_AH) + warp * 8;

    const int row = lane & 7;                  // my row within the slot
    const int q   = lane >> 3;                 // quarter of the row (0..3)
    const int cbase  = (q == 0) ? 0 : (1 + 6 * q);   // 0,7,13,19
    const int ccount = (q == 0) ? 7 : 6;

    #pragma unroll 1
    for (int g = 0; g < myCount; g++) {
        const int slot = g & 1;
        const uint32_t mb = mbar_b + (uint32_t)(warp * 2 + slot) * 8;
        mbar_wait(mb, (unsigned)((g >> 1) & 1));

        const char* sl = dyn + (warp * 2 + slot) * SLOT_SZ;

        // ---- PASS 1: quarter-row-per-lane dot ----
        const ulonglong2* myrow = (const ulonglong2*)(sl + row * 400) + cbase;
        const ulonglong2* thq   = thp + cbase;
        u64 a0 = Z64, a1 = Z64;
        #pragma unroll
        for (int j = 0; j < 6; j++) {
            ulonglong2 x = myrow[j];
            ulonglong2 t = thq[j];
            a0 = ffma2(x.x, t.x, a0); a1 = ffma2(x.y, t.y, a1);
        }
        if (ccount == 7) {
            ulonglong2 x = myrow[6];
            ulonglong2 t = thq[6];
            a0 = ffma2(x.x, t.x, a0); a1 = ffma2(x.y, t.y, a1);
        }
        float l0, h0, l1, h1;
        unpack2(a0, l0, h0); unpack2(a1, l1, h1);
        float v = (l0 + h0) + (l1 + h1);
        v += __shfl_xor_sync(FULL, v, 8);
        v += __shfl_xor_sync(FULL, v, 16);      // full 100-dot of my row

        const int m = ((const int*)(sl + SLOT_X))[row];
        // k pattern repeats every 50 slots (50*8 = 400 rows)
        const int smod = (myStart + g) % 50;
        const int k = smod * 8 + row;
        const float pf = __ldg(phi_fr + k);

        const float r   = __expf(v);            // non_linearity = exp
        const float dtr = dt * r;
        // 1 - e^-dtr = (E-1)/E  =>  llc = log(E-1) - dtr  (one exp)
        const float Em1  = __expf(dtr) - 1.0f;
        const float w_m  = __fdividef(dtr, Em1 - EPSF);
        const float ll_m = __logf(Em1 + EPSF) - dtr;
        const float w    = m ? w_m  : -dtr;
        const float llc  = m ? ll_m : -dtr;

        p1acc += pf * llc;                      // 4x redundant; *0.25 at end
        p2acc += pf * pf * llc;
        if (lane < 8) {
            const float A = pf * w;
            ahp[lane] = make_float2(A, pf * A);
        }
        __syncwarp();

        // ---- PASS 2: lane-per-column accumulation (4 FFMA2 / row) ----
        if (lane < 25) {
            #pragma unroll
            for (int rr = 0; rr < 8; rr++) {
                const float2 ah = ahp[rr];                       // broadcast
                const ulonglong2 x =
                    ((const ulonglong2*)(sl + rr * 400))[lane];
                const u64 Au = pack2(ah.x, ah.x);
                const u64 Hu = pack2(ah.y, ah.y);
                Ga01 = ffma2(Au, x.x, Ga01); Ga23 = ffma2(Au, x.y, Ga23);
                Ha01 = ffma2(Hu, x.x, Ha01); Ha23 = ffma2(Hu, x.y, Ha23);
            }
        }
        __syncwarp();
        if (lane == 0 && g + 2 < myCount) issue(g + 2);
    }

    #pragma unroll
    for (int o = 16; o; o >>= 1) {
        p1acc += __shfl_xor_sync(FULL, p1acc, o);
        p2acc += __shfl_xor_sync(FULL, p2acc, o);
    }
    p1acc *= 0.25f; p2acc *= 0.25f;

    if (lane < 25) {
        float g0, g1, g2, g3, h0, h1, h2, h3;
        unpack2(Ga01, g0, g1); unpack2(Ga23, g2, g3);
        unpack2(Ha01, h0, h1); unpack2(Ha23, h2, h3);
        *(float4*)&sga[warp][lane * 4] = make_float4(g0, g1, g2, g3);
        *(float4*)&sha[warp][lane * 4] = make_float4(h0, h1, h2, h3);
    }
    if (lane == 0) { sp[warp][0] = p1acc; sp[warp][1] = p2acc; }
    __syncthreads();

    if (tid < A_DIM) {
        const float ga = sga[0][tid] + sga[1][tid] + sga[2][tid] + sga[3][tid];
        const float ha = sha[0][tid] + sha[1][tid] + sha[2][tid] + sha[3][tid];
        atomicAdd(&d_acc[tid],         ga);
        atomicAdd(&d_acc[A_DIM + tid], ha);
    }
    if (tid == 0)
        atomicAdd(&d_acc[2 * A_DIM],     sp[0][0] + sp[1][0] + sp[2][0] + sp[3][0]);
    if (tid == 1)
        atomicAdd(&d_acc[2 * A_DIM + 1], sp[0][1] + sp[1][1] + sp[2][1] + sp[3][1]);

    // ---- last-block-done fused finalize ----
    __threadfence();
    __shared__ bool amlast;
    if (tid == 0) amlast = (atomicAdd(&d_done, 1u) == (unsigned)(gridDim.x - 1));
    __syncthreads();
    if (!amlast) return;

    volatile float* vacc = d_acc;
    float Ga = 0.f, Ha = 0.f;
    if (tid < A_DIM) { Ga = vacc[tid]; Ha = vacc[A_DIM + tid]; }
    const float P1 = vacc[2 * A_DIM], P2 = vacc[2 * A_DIM + 1];

    float b0 = 0.f, b1 = 0.f, b2 = 0.f, b3 = 0.f;
    for (int i = tid; i < KFR; i += 128) {
        const float pfv = phi_fr[i], pdv = phi_d[i];
        b0 += pfv; b1 += pfv * pfv; b2 += pdv; b3 += pdv * pdv;
    }
    #pragma unroll
    for (int o = 16; o; o >>= 1) {
        b0 += __shfl_xor_sync(FULL, b0, o);
        b1 += __shfl_xor_sync(FULL, b1, o);
        b2 += __shfl_xor_sync(FULL, b2, o);
        b3 += __shfl_xor_sync(FULL, b3, o);
    }
    __shared__ float shp[4][4];
    __shared__ float sc[4];
    if (lane == 0) { shp[warp][0] = b0; shp[warp][1] = b1;
                     shp[warp][2] = b2; shp[warp][3] = b3; }
    __syncthreads();

    // clean state for the next graph replay
    if (tid < A_DIM) { d_acc[tid] = 0.f; d_acc[A_DIM + tid] = 0.f; }
    if (tid == A_DIM) { d_acc[2 * A_DIM] = 0.f; d_acc[2 * A_DIM + 1] = 0.f;
                        d_done = 0u; }

    if (tid < 4) sc[tid] = shp[0][tid] + shp[1][tid] + shp[2][tid] + shp[3][tid];
    __syncthreads();

    const float S_fr = sc[0], Q_fr = sc[1], S_d = sc[2], Q_d = sc[3];
    const float n_fr = 0.5f * (float)KFR * (float)(KFR - 1);
    const float n_d  = 0.5f * (float)KD  * (float)(KD - 1);
    const float inv_kdkfr = 1.0f / ((float)KD * (float)KFR);

    if (tid == 0) {
        out[0] = (P1 * S_fr - P2) / n_fr - 2.0f * S_d * P1 * inv_kdkfr;
        out[1 + A_DIM] = (S_d * S_d - Q_d) / (2.0f * n_d)
                       + (S_fr * S_fr - Q_fr) / (2.0f * n_fr)
                       - 2.0f * S_d * S_fr * inv_kdkfr;
    }
    if (tid < A_DIM) {
        out[1 + tid] = (S_fr * Ga - Ha) / n_fr - 2.0f * S_d * Ga * inv_kdkfr;
    }
}

extern "C" void kernel_launch(void* const* d_in, const int* in_sizes, int n_in,
                              void* d_out, int out_size) {
    const float* t      = (const float*)d_in[0];
    const int*   mask   = (const int*)  d_in[1];
    const float* X      = (const float*)d_in[2];
    const float* theta  = (const float*)d_in[3];
    const float* phi_d  = (const float*)d_in[4];
    const float* phi_fr = (const float*)d_in[5];
    float* out = (float*)d_out;

    cudaFuncSetAttribute(mmdglm_main,
                         cudaFuncAttributeMaxDynamicSharedMemorySize, DYN_SZ);
    mmdglm_main<<<GRID, 128, DYN_SZ>>>(t, mask, X, theta, phi_fr, phi_d, out);
}

// round 17
// speedup vs baseline: 1.0452x; 1.0452x over previous
#include <cuda_runtime.h>
#include <cstdint>

#define T_DIM    2000
#define KFR      400
#define KD       400
#define A_DIM    100
#define NSLOT    50000                 // 16-row slots total (800000 rows)
#define GRID     592                   // 4 blocks/SM * 148 SMs: exactly one wave
#define NWARPS   (GRID * 4)            // 2368
#define BASEW    21                    // NSLOT / NWARPS
#define EXTRA    272                   // first 272 warps get 22 slots
#define SLOT_X   6400                  // 16 rows * 400B (one bulk DMA)
#define SLOT_SZ  6528                  // + 64B mask + pad (16B aligned)
#define TXB      6464u
#define OFF_TH   (4 * 2 * SLOT_SZ)                 // 52224
#define OFF_AH   (OFF_TH + 416)                    // 52640
#define OFF_MBAR (OFF_AH + 512)                    // 53152
#define DYN_SZ   (OFF_MBAR + 64)                   // 53216
#define EPSF     1e-24f

typedef unsigned long long u64;

__device__ __forceinline__ u64 pack2(float lo, float hi) {
    u64 r; asm("mov.b64 %0, {%1, %2};" : "=l"(r) : "f"(lo), "f"(hi)); return r;
}
__device__ __forceinline__ void unpack2(u64 v, float& lo, float& hi) {
    asm("mov.b64 {%0, %1}, %2;" : "=f"(lo), "=f"(hi) : "l"(v));
}
__device__ __forceinline__ u64 ffma2(u64 a, u64 b, u64 c) {
    u64 d; asm("fma.rn.f32x2 %0, %1, %2, %3;" : "=l"(d) : "l"(a), "l"(b), "l"(c));
    return d;
}
__device__ __forceinline__ void mbar_wait(uint32_t mbar, uint32_t parity) {
    asm volatile(
        "{\n\t.reg .pred P;\n\t"
        "W_%=:\n\t"
        "mbarrier.try_wait.parity.acquire.cta.shared::cta.b64 P, [%0], %1, 0x989680;\n\t"
        "@!P bra W_%=;\n\t}"
        :: "r"(mbar), "r"(parity) : "memory");
}

// Accumulators: [0..99]=Ga, [100..199]=Ha, [200]=P1, [201]=P2. Self-cleaning.
__device__ float d_acc[2 * A_DIM + 2];
__device__ unsigned int d_done;

// FINAL (R13 configuration — sits at the measured platform ceiling for this
// DMA-streamed read pattern; occupancy/stream/slot/prefetch perturbations
// all measured worse in R14-R16).
// Exact-capacity grid: 592 blocks = 4/SM, one perfectly-filled wave. The
// 50000 16-row slots are split statically: warp w owns 21 or 22 CONSECUTIVE
// slots (start = 21w + min(w,272)). Each slot: one 6.4KB bulk-DMA into a
// 2-deep private ring with per-slot mbarrier (no block sync). PASS 1: lanes
// r and r+16 split row r's 100-dot (13/12 chunks), one shfl_xor(16) merges;
// one exp/log/div warp-op serves 16 rows; per-lane exact phi_k. PASS 2:
// lane-per-column, (A,H) broadcast via LDS.64, 4 FFMA2 per row. Fused
// last-block finalize, self-cleaning for graph replay.
__global__ __launch_bounds__(128) void mmdglm_main(
    const float* __restrict__ tg, const int* __restrict__ mask,
    const float* __restrict__ X, const float* __restrict__ theta,
    const float* __restrict__ phi_fr, const float* __restrict__ phi_d,
    float* __restrict__ out)
{
    extern __shared__ __align__(16) char dyn[];
    __shared__ float sga[4][A_DIM];
    __shared__ float sha[4][A_DIM];
    __shared__ float sp[4][2];

    const int warp  = threadIdx.x >> 5;
    const int lane  = threadIdx.x & 31;
    const int tid   = threadIdx.x;
    const float dt  = tg[1] - tg[0];
    const unsigned FULL = 0xffffffffu;
    const u64 Z64 = 0ull;

    const uint32_t dyn_b  = (uint32_t)__cvta_generic_to_shared(dyn);
    const uint32_t mbar_b = dyn_b + OFF_MBAR;

    // theta -> smem broadcast table
    if (tid < A_DIM) *(float*)(dyn + OFF_TH + tid * 4) = __ldg(theta + tid);

    if (tid < 8) {
        asm volatile("mbarrier.init.shared.b64 [%0], 1;"
                     :: "r"(mbar_b + tid * 8) : "memory");
    }
    asm volatile("fence.proxy.async.shared::cta;" ::: "memory");
    __syncthreads();

    // static balanced slot range for this warp
    const int gw      = blockIdx.x * 4 + warp;
    const int myStart = BASEW * gw + (gw < EXTRA ? gw : EXTRA);
    const int myCount = BASEW + (gw < EXTRA ? 1 : 0);

    const char* gX = (const char*)X;
    const char* gM = (const char*)mask;

    auto issue = [&](int g) {
        const int slot = g & 1;
        const uint32_t sd = dyn_b + (uint32_t)(warp * 2 + slot) * SLOT_SZ;
        const uint32_t mb = mbar_b + (uint32_t)(warp * 2 + slot) * 8;
        const size_t sid = (size_t)(myStart + g);
        asm volatile("mbarrier.arrive.expect_tx.shared.b64 _, [%0], %1;"
                     :: "r"(mb), "r"(TXB) : "memory");
        asm volatile("cp.async.bulk.shared::cta.global.mbarrier::complete_tx::bytes"
                     " [%0], [%1], %2, [%3];"
                     :: "r"(sd), "l"(gX + sid * SLOT_X), "n"(SLOT_X), "r"(mb) : "memory");
        asm volatile("cp.async.bulk.shared::cta.global.mbarrier::complete_tx::bytes"
                     " [%0], [%1], %2, [%3];"
                     :: "r"(sd + SLOT_X), "l"(gM + sid * 64), "n"(64), "r"(mb) : "memory");
    };

    if (lane == 0) { issue(0); if (myCount > 1) issue(1); }

    u64 Ga01 = Z64, Ga23 = Z64, Ha01 = Z64, Ha23 = Z64;
    float p1acc = 0.f, p2acc = 0.f;

    const ulonglong2* thp = (const ulonglong2*)(dyn + OFF_TH);
    float2* ahp = (float2*)(dyn + OFF_AH) + warp * 16;

    const int row    = lane & 15;             // my row within the slot
    const int cbase  = (lane < 16) ? 0 : 13;  // chunk split: 13 / 12
    const int ccount = (lane < 16) ? 13 : 12;

    #pragma unroll 1
    for (int g = 0; g < myCount; g++) {
        const int slot = g & 1;
        const uint32_t mb = mbar_b + (uint32_t)(warp * 2 + slot) * 8;
        mbar_wait(mb, (unsigned)((g >> 1) & 1));

        const char* sl = dyn + (warp * 2 + slot) * SLOT_SZ;

        // ---- PASS 1: half-row-per-lane dot ----
        const ulonglong2* myrow = (const ulonglong2*)(sl + row * 400) + cbase;
        const ulonglong2* thq   = thp + cbase;
        u64 a0 = Z64, a1 = Z64;
        #pragma unroll
        for (int j = 0; j < 12; j++) {
            ulonglong2 x = myrow[j];
            ulonglong2 t = thq[j];
            a0 = ffma2(x.x, t.x, a0); a1 = ffma2(x.y, t.y, a1);
        }
        if (ccount == 13) {
            ulonglong2 x = myrow[12];
            ulonglong2 t = thq[12];
            a0 = ffma2(x.x, t.x, a0); a1 = ffma2(x.y, t.y, a1);
        }
        float l0, h0, l1, h1;
        unpack2(a0, l0, h0); unpack2(a1, l1, h1);
        float v = (l0 + h0) + (l1 + h1);
        v += __shfl_xor_sync(FULL, v, 16);      // full 100-dot of my row

        const int m = ((const int*)(sl + SLOT_X))[row];
        // k pattern repeats every 25 slots (25*16 = 400 rows)
        const int smod = (myStart + g) % 25;
        const int k = smod * 16 + row;
        const float pf = __ldg(phi_fr + k);

        const float r   = __expf(v);            // non_linearity = exp
        const float dtr = dt * r;
        // 1 - e^-dtr = (E-1)/E  =>  llc = log(E-1) - dtr  (one exp)
        const float Em1  = __expf(dtr) - 1.0f;
        const float w_m  = __fdividef(dtr, Em1 - EPSF);
        const float ll_m = __logf(Em1 + EPSF) - dtr;
        const float w    = m ? w_m  : -dtr;
        const float llc  = m ? ll_m : -dtr;

        p1acc += pf * llc;                      // 2x redundant; *0.5 at end
        p2acc += pf * pf * llc;
        if (lane < 16) {
            const float A = pf * w;
            ahp[lane] = make_float2(A, pf * A);
        }
        __syncwarp();

        // ---- PASS 2: lane-per-column accumulation (4 FFMA2 / row) ----
        if (lane < 25) {
            #pragma unroll 4
            for (int rr = 0; rr < 16; rr++) {
                const float2 ah = ahp[rr];                       // broadcast
                const ulonglong2 x =
                    ((const ulonglong2*)(sl + rr * 400))[lane];
                const u64 Au = pack2(ah.x, ah.x);
                const u64 Hu = pack2(ah.y, ah.y);
                Ga01 = ffma2(Au, x.x, Ga01); Ga23 = ffma2(Au, x.y, Ga23);
                Ha01 = ffma2(Hu, x.x, Ha01); Ha23 = ffma2(Hu, x.y, Ha23);
            }
        }
        __syncwarp();
        if (lane == 0 && g + 2 < myCount) issue(g + 2);
    }

    #pragma unroll
    for (int o = 16; o; o >>= 1) {
        p1acc += __shfl_xor_sync(FULL, p1acc, o);
        p2acc += __shfl_xor_sync(FULL, p2acc, o);
    }
    p1acc *= 0.5f; p2acc *= 0.5f;

    if (lane < 25) {
        float g0, g1, g2, g3, h0, h1, h2, h3;
        unpack2(Ga01, g0, g1); unpack2(Ga23, g2, g3);
        unpack2(Ha01, h0, h1); unpack2(Ha23, h2, h3);
        *(float4*)&sga[warp][lane * 4] = make_float4(g0, g1, g2, g3);
        *(float4*)&sha[warp][lane * 4] = make_float4(h0, h1, h2, h3);
    }
    if (lane == 0) { sp[warp][0] = p1acc; sp[warp][1] = p2acc; }
    __syncthreads();

    if (tid < A_DIM) {
        const float ga = sga[0][tid] + sga[1][tid] + sga[2][tid] + sga[3][tid];
        const float ha = sha[0][tid] + sha[1][tid] + sha[2][tid] + sha[3][tid];
        atomicAdd(&d_acc[tid],         ga);
        atomicAdd(&d_acc[A_DIM + tid], ha);
    }
    if (tid == 0)
        atomicAdd(&d_acc[2 * A_DIM],     sp[0][0] + sp[1][0] + sp[2][0] + sp[3][0]);
    if (tid == 1)
        atomicAdd(&d_acc[2 * A_DIM + 1], sp[0][1] + sp[1][1] + sp[2][1] + sp[3][1]);

    // ---- last-block-done fused finalize ----
    __threadfence();
    __shared__ bool amlast;
    if (tid == 0) amlast = (atomicAdd(&d_done, 1u) == (unsigned)(gridDim.x - 1));
    __syncthreads();
    if (!amlast) return;

    volatile float* vacc = d_acc;
    float Ga = 0.f, Ha = 0.f;
    if (tid < A_DIM) { Ga = vacc[tid]; Ha = vacc[A_DIM + tid]; }
    const float P1 = vacc[2 * A_DIM], P2 = vacc[2 * A_DIM + 1];

    float b0 = 0.f, b1 = 0.f, b2 = 0.f, b3 = 0.f;
    for (int i = tid; i < KFR; i += 128) {
        const float pfv = phi_fr[i], pdv = phi_d[i];
        b0 += pfv; b1 += pfv * pfv; b2 += pdv; b3 += pdv * pdv;
    }
    #pragma unroll
    for (int o = 16; o; o >>= 1) {
        b0 += __shfl_xor_sync(FULL, b0, o);
        b1 += __shfl_xor_sync(FULL, b1, o);
        b2 += __shfl_xor_sync(FULL, b2, o);
        b3 += __shfl_xor_sync(FULL, b3, o);
    }
    __shared__ float shp[4][4];
    __shared__ float sc[4];
    if (lane == 0) { shp[warp][0] = b0; shp[warp][1] = b1;
                     shp[warp][2] = b2; shp[warp][3] = b3; }
    __syncthreads();

    // clean state for the next graph replay
    if (tid < A_DIM) { d_acc[tid] = 0.f; d_acc[A_DIM + tid] = 0.f; }
    if (tid == A_DIM) { d_acc[2 * A_DIM] = 0.f; d_acc[2 * A_DIM + 1] = 0.f;
                        d_done = 0u; }

    if (tid < 4) sc[tid] = shp[0][tid] + shp[1][tid] + shp[2][tid] + shp[3][tid];
    __syncthreads();

    const float S_fr = sc[0], Q_fr = sc[1], S_d = sc[2], Q_d = sc[3];
    const float n_fr = 0.5f * (float)KFR * (float)(KFR - 1);
    const float n_d  = 0.5f * (float)KD  * (float)(KD - 1);
    const float inv_kdkfr = 1.0f / ((float)KD * (float)KFR);

    if (tid == 0) {
        out[0] = (P1 * S_fr - P2) / n_fr - 2.0f * S_d * P1 * inv_kdkfr;
        out[1 + A_DIM] = (S_d * S_d - Q_d) / (2.0f * n_d)
                       + (S_fr * S_fr - Q_fr) / (2.0f * n_fr)
                       - 2.0f * S_d * S_fr * inv_kdkfr;
    }
    if (tid < A_DIM) {
        out[1 + tid] = (S_fr * Ga - Ha) / n_fr - 2.0f * S_d * Ga * inv_kdkfr;
    }
}

extern "C" void kernel_launch(void* const* d_in, const int* in_sizes, int n_in,
                              void* d_out, int out_size) {
    const float* t      = (const float*)d_in[0];
    const int*   mask   = (const int*)  d_in[1];
    const float* X      = (const float*)d_in[2];
    const float* theta  = (const float*)d_in[3];
    const float* phi_d  = (const float*)d_in[4];
    const float* phi_fr = (const float*)d_in[5];
    float* out = (float*)d_out;

    cudaFuncSetAttribute(mmdglm_main,
                         cudaFuncAttributeMaxDynamicSharedMemorySize, DYN_SZ);
    mmdglm_main<<<GRID, 128, DYN_SZ>>>(t, mask, X, theta, phi_fr, phi_d, out);
}